// round 8
// baseline (speedup 1.0000x reference)
#include <cuda_runtime.h>
#include <cstdint>

// Shapes (fixed per reference setup_inputs)
#define C_  256
#define OUT_PER_B (1 << 22)              // 128*128*256
#define IN_PER_B  (1 << 20)              // 64*64*256

#define NCHUNK           8
#define CHUNK_OUT_F      (2 * OUT_PER_B)             // 8,388,608 floats (2 batches)
#define CHUNK_OUT_F4     (CHUNK_OUT_F / 4)           // 2,097,152 float4
#define CHUNK_GROUPS     ((2 * IN_PER_B) / 4)        // 524,288 groups of 4

// scatter grid: exactly 2 groups per thread
#define SBLOCKS   1024
#define STHREADS  256
#define SNTHREADS (SBLOCKS * STHREADS)               // 262,144

// zero grid
#define ZBLOCKS   512
#define ZTHREADS  256
#define ZNTHREADS (ZBLOCKS * ZTHREADS)               // 131,072
#define ZITERS    (CHUNK_OUT_F4 / ZNTHREADS)         // 16

__global__ void __launch_bounds__(ZTHREADS) zero_chunk_kernel(float4* __restrict__ dst) {
    int tid = blockIdx.x * ZTHREADS + threadIdx.x;
    float4 z = make_float4(0.f, 0.f, 0.f, 0.f);
#pragma unroll
    for (int j = 0; j < ZITERS; j++)
        dst[tid + j * ZNTHREADS] = z;
}

// Pure scatter: 2 independent groups (8 elements, 8 REDs) per thread.
__global__ void __launch_bounds__(STHREADS) scatter_chunk_kernel(
        const float4* __restrict__ updates4,
        const int4*   __restrict__ mask4,
        float*        __restrict__ out,
        int chunk) {
    int tid = blockIdx.x * STHREADS + threadIdx.x;
    int g0 = chunk * CHUNK_GROUPS + tid;
    int g1 = g0 + SNTHREADS;

    int4   ma = mask4[g0];
    float4 ua = updates4[g0];
    int4   mb = mask4[g1];
    float4 ub = updates4[g1];

    // dest = out + b*OUT_PER_B + (mask & ~(C-1)) + channel(lane)
    int e0a = g0 << 2;
    int e0b = g1 << 2;
    float* oa = out + ((size_t)(e0a >> 20) << 22) + (e0a & (C_ - 1));
    float* ob = out + ((size_t)(e0b >> 20) << 22) + (e0b & (C_ - 1));

    atomicAdd(oa + (ma.x & ~(C_ - 1)) + 0, ua.x);
    atomicAdd(oa + (ma.y & ~(C_ - 1)) + 1, ua.y);
    atomicAdd(oa + (ma.z & ~(C_ - 1)) + 2, ua.z);
    atomicAdd(oa + (ma.w & ~(C_ - 1)) + 3, ua.w);
    atomicAdd(ob + (mb.x & ~(C_ - 1)) + 0, ub.x);
    atomicAdd(ob + (mb.y & ~(C_ - 1)) + 1, ub.y);
    atomicAdd(ob + (mb.z & ~(C_ - 1)) + 2, ub.z);
    atomicAdd(ob + (mb.w & ~(C_ - 1)) + 3, ub.w);
}

extern "C" void kernel_launch(void* const* d_in, const int* in_sizes, int n_in,
                              void* d_out, int out_size) {
    const float4* updates4 = (const float4*)d_in[0];
    const int4*   mask4    = (const int4*)d_in[1];
    float*        out      = (float*)d_out;

    // One-time host resources (handles only; no device memory allocation).
    static cudaStream_t zs = nullptr;   // zero chain
    static cudaStream_t ss = nullptr;   // scatter chain
    static cudaEvent_t  evFork = nullptr, evJoin = nullptr;
    static cudaEvent_t  evZero[NCHUNK];
    if (zs == nullptr) {
        cudaStreamCreateWithFlags(&zs, cudaStreamNonBlocking);
        cudaStreamCreateWithFlags(&ss, cudaStreamNonBlocking);
        cudaEventCreateWithFlags(&evFork, cudaEventDisableTiming);
        cudaEventCreateWithFlags(&evJoin, cudaEventDisableTiming);
        for (int c = 0; c < NCHUNK; c++)
            cudaEventCreateWithFlags(&evZero[c], cudaEventDisableTiming);
    }

    // Fork from the capture (legacy) stream into two independent branches.
    cudaEventRecord(evFork, 0);
    cudaStreamWaitEvent(zs, evFork, 0);
    cudaStreamWaitEvent(ss, evFork, 0);

    // Branch 1: zero chain (non-blocking stream; no implicit sync with ss).
    for (int c = 0; c < NCHUNK; c++) {
        float4* region = (float4*)(out + (size_t)c * CHUNK_OUT_F);
        zero_chunk_kernel<<<ZBLOCKS, ZTHREADS, 0, zs>>>(region);
        cudaEventRecord(evZero[c], zs);
    }

    // Branch 2: scatter chain; scatter(c) gated only on zero(c).
    for (int c = 0; c < NCHUNK; c++) {
        cudaStreamWaitEvent(ss, evZero[c], 0);
        scatter_chunk_kernel<<<SBLOCKS, STHREADS, 0, ss>>>(updates4, mask4, out, c);
    }

    // Join both branches back into the capture stream.
    cudaEventRecord(evJoin, ss);        // ss already depends on all of zs's work
    cudaStreamWaitEvent(0, evJoin, 0);
}